// round 1
// baseline (speedup 1.0000x reference)
#include <cuda_runtime.h>
#include <cuda_bf16.h>
#include <math.h>

// ---------------------------------------------------------------------------
// GraphEncoder pipeline, fp32 baseline.
// Shapes: B=16, N=1024, H=256, F=400, heads=4, Dh=64.
// Segments for attention: [0,512) [512,768) [768,1024).
// ---------------------------------------------------------------------------

#define BATCH 16
#define SEQ   1024
#define HID   256
#define FF    400
#define QKVW  768
#define ROWS  (BATCH * SEQ)          // 16384

// -------------------- scratch (static device memory; no allocs) ------------
__device__ float g_bufA[ROWS * HID];     // 16 MB
__device__ float g_bufB[ROWS * HID];     // 16 MB
__device__ float g_bufC[ROWS * HID];     // 16 MB
__device__ float g_qkv [ROWS * QKVW];    // 48 MB
__device__ float g_ff  [ROWS * FF];      // 25 MB
__device__ float g_m   [BATCH * HID];    // 16 KB

// -------------------- gather: h0[row] = emb[idx[row]] ----------------------
__global__ void __launch_bounds__(256) gather_kernel(
    const int* __restrict__ idx, const float* __restrict__ emb,
    float* __restrict__ h0)
{
    int row = blockIdx.x;
    int tid = threadIdx.x;
    int e = __ldg(&idx[row]);
    h0[(long long)row * HID + tid] = __ldg(&emb[(long long)e * HID + tid]);
}

// -------------------- generic NN GEMM: C = A@B (+bias)(+relu) --------------
// BM=128, BN=64, BK=16, 256 threads, 8x4 per thread.
// Requirements (all satisfied here): M % 128 == 0, K % 16 == 0, N % 4 == 0,
// lda/ldb/ldc % 4 == 0.
#define GBM 128
#define GBN 64
#define GBK 16

__global__ void __launch_bounds__(256) gemm_nn(
    const float* __restrict__ A, const float* __restrict__ B,
    const float* __restrict__ bias, float* __restrict__ C,
    int M, int N, int K, int lda, int ldb, int ldc,
    long long sA, long long sB, long long sC, int relu)
{
    const long long bz = blockIdx.z;
    A += bz * sA;  B += bz * sB;  C += bz * sC;

    const int m0 = blockIdx.y * GBM;
    const int n0 = blockIdx.x * GBN;

    __shared__ float As[GBK][GBM];
    __shared__ float Bs[GBK][GBN];

    const int tid  = threadIdx.x;
    const int trow = tid >> 4;          // 0..15 -> 8 rows each
    const int tcol = tid & 15;          // 0..15 -> 4 cols each

    const int ar0 = tid >> 2;           // 0..63 (row, two passes of 64)
    const int ak4 = tid & 3;            // float4 index within 16-wide k
    const int bk  = tid >> 4;           // 0..15
    const int bn4 = tid & 15;           // 0..15 -> col n0 + bn4*4

    float acc[8][4];
    #pragma unroll
    for (int i = 0; i < 8; i++)
        #pragma unroll
        for (int j = 0; j < 4; j++) acc[i][j] = 0.f;

    for (int k0 = 0; k0 < K; k0 += GBK) {
        // ---- load A tile (128x16) as float4, store transposed ----
        #pragma unroll
        for (int i = 0; i < 2; i++) {
            int r = ar0 + i * 64;
            const float4 v = *reinterpret_cast<const float4*>(
                &A[(long long)(m0 + r) * lda + k0 + ak4 * 4]);
            As[ak4 * 4 + 0][r] = v.x;
            As[ak4 * 4 + 1][r] = v.y;
            As[ak4 * 4 + 2][r] = v.z;
            As[ak4 * 4 + 3][r] = v.w;
        }
        // ---- load B tile (16x64) as float4 ----
        {
            int gn = n0 + bn4 * 4;
            float4 v = make_float4(0.f, 0.f, 0.f, 0.f);
            if (gn < N)
                v = *reinterpret_cast<const float4*>(
                    &B[(long long)(k0 + bk) * ldb + gn]);
            *reinterpret_cast<float4*>(&Bs[bk][bn4 * 4]) = v;
        }
        __syncthreads();

        #pragma unroll
        for (int k = 0; k < GBK; k++) {
            float a[8], b[4];
            #pragma unroll
            for (int i = 0; i < 8; i++) a[i] = As[k][trow * 8 + i];
            #pragma unroll
            for (int j = 0; j < 4; j++) b[j] = Bs[k][tcol * 4 + j];
            #pragma unroll
            for (int i = 0; i < 8; i++)
                #pragma unroll
                for (int j = 0; j < 4; j++)
                    acc[i][j] += a[i] * b[j];
        }
        __syncthreads();
    }

    #pragma unroll
    for (int j = 0; j < 4; j++) {
        int gn = n0 + tcol * 4 + j;
        if (gn >= N) continue;
        float bv = bias ? bias[gn] : 0.f;
        #pragma unroll
        for (int i = 0; i < 8; i++) {
            int gm = m0 + trow * 8 + i;
            float v = acc[i][j] + bv;
            if (relu) v = fmaxf(v, 0.f);
            C[(long long)gm * ldc + gn] = v;
        }
    }
}

// -------------------- block-diagonal attention -----------------------------
// grid (32 qtiles, 4 heads, 16 batch), 256 threads, qtile = 32 queries.
// Full softmax row kept in smem (max S = 512).
__global__ void __launch_bounds__(256) attn_kernel(
    const float* __restrict__ qkv, float* __restrict__ ctx)
{
    extern __shared__ float smem[];
    const int qt = blockIdx.x, h = blockIdx.y, b = blockIdx.z;
    const int qstart = qt * 32;
    int kstart, S;
    if      (qstart < 512) { kstart = 0;   S = 512; }
    else if (qstart < 768) { kstart = 512; S = 256; }
    else                   { kstart = 768; S = 256; }

    float* sQT = smem;                 // [64][33]  q transposed
    float* sKV = sQT + 64 * 33;        // [32][68]  k/v chunk
    float* sS  = sKV + 32 * 68;        // [32][S]   scores / probs

    const int tid = threadIdx.x;
    const long long rowbase = (long long)(b * SEQ) * QKVW;

    // load Q tile transposed
    #pragma unroll
    for (int i = 0; i < 8; i++) {
        int flat = tid + i * 256;
        int qi = flat >> 6, d = flat & 63;
        sQT[d * 33 + qi] =
            qkv[rowbase + (long long)(qstart + qi) * QKVW + h * 64 + d];
    }
    __syncthreads();

    // ---- scores = (Q K^T) * 0.125 ----
    const int sqi  = tid & 31;
    const int skj0 = (tid >> 5) * 4;
    for (int kc = 0; kc < S; kc += 32) {
        #pragma unroll
        for (int i = 0; i < 8; i++) {
            int flat = tid + i * 256;
            int ki = flat >> 6, d = flat & 63;
            sKV[ki * 68 + d] =
                qkv[rowbase + (long long)(kstart + kc + ki) * QKVW + 256 + h * 64 + d];
        }
        __syncthreads();
        float a0 = 0.f, a1 = 0.f, a2 = 0.f, a3 = 0.f;
        #pragma unroll 16
        for (int d = 0; d < 64; d++) {
            float qv = sQT[d * 33 + sqi];
            a0 += qv * sKV[(skj0 + 0) * 68 + d];
            a1 += qv * sKV[(skj0 + 1) * 68 + d];
            a2 += qv * sKV[(skj0 + 2) * 68 + d];
            a3 += qv * sKV[(skj0 + 3) * 68 + d];
        }
        sS[sqi * S + kc + skj0 + 0] = a0 * 0.125f;
        sS[sqi * S + kc + skj0 + 1] = a1 * 0.125f;
        sS[sqi * S + kc + skj0 + 2] = a2 * 0.125f;
        sS[sqi * S + kc + skj0 + 3] = a3 * 0.125f;
        __syncthreads();
    }

    // ---- softmax per row (1 warp per row, 4 rows per warp) ----
    {
        const int warp = tid >> 5, lane = tid & 31;
        for (int qi = warp; qi < 32; qi += 8) {
            float* row = sS + qi * S;
            float mx = -1e30f;
            for (int j = lane; j < S; j += 32) mx = fmaxf(mx, row[j]);
            #pragma unroll
            for (int o = 16; o; o >>= 1) mx = fmaxf(mx, __shfl_xor_sync(~0u, mx, o));
            float sum = 0.f;
            for (int j = lane; j < S; j += 32) {
                float e = __expf(row[j] - mx);
                row[j] = e;
                sum += e;
            }
            #pragma unroll
            for (int o = 16; o; o >>= 1) sum += __shfl_xor_sync(~0u, sum, o);
            float inv = 1.f / sum;
            for (int j = lane; j < S; j += 32) row[j] *= inv;
        }
    }
    __syncthreads();

    // ---- ctx = P @ V ----
    const int cqi = tid >> 3;            // 0..31
    const int cd0 = (tid & 7) * 8;       // 0..56
    float acc[8];
    #pragma unroll
    for (int u = 0; u < 8; u++) acc[u] = 0.f;

    for (int kc = 0; kc < S; kc += 32) {
        #pragma unroll
        for (int i = 0; i < 8; i++) {
            int flat = tid + i * 256;
            int ki = flat >> 6, d = flat & 63;
            sKV[ki * 68 + d] =
                qkv[rowbase + (long long)(kstart + kc + ki) * QKVW + 512 + h * 64 + d];
        }
        __syncthreads();
        #pragma unroll 8
        for (int ki = 0; ki < 32; ki++) {
            float p = sS[cqi * S + kc + ki];
            #pragma unroll
            for (int u = 0; u < 8; u++)
                acc[u] += p * sKV[ki * 68 + cd0 + u];
        }
        __syncthreads();
    }

    #pragma unroll
    for (int u = 0; u < 8; u++)
        ctx[(long long)(b * SEQ + qstart + cqi) * HID + h * 64 + cd0 + u] = acc[u];
}

// -------------------- residual add + layernorm -----------------------------
__global__ void __launch_bounds__(256) add_ln_kernel(
    const float* __restrict__ X, const float* __restrict__ Yd,
    const float* __restrict__ g, const float* __restrict__ bb,
    float* __restrict__ out)
{
    const int row = blockIdx.x;
    const int tid = threadIdx.x;
    __shared__ float red[8];

    float v = X[(long long)row * HID + tid] + Yd[(long long)row * HID + tid];

    float s = v;
    #pragma unroll
    for (int o = 16; o; o >>= 1) s += __shfl_xor_sync(~0u, s, o);
    if ((tid & 31) == 0) red[tid >> 5] = s;
    __syncthreads();
    float mu = 0.f;
    #pragma unroll
    for (int i = 0; i < 8; i++) mu += red[i];
    mu *= (1.f / 256.f);
    __syncthreads();

    float dv = v - mu;
    float s2 = dv * dv;
    #pragma unroll
    for (int o = 16; o; o >>= 1) s2 += __shfl_xor_sync(~0u, s2, o);
    if ((tid & 31) == 0) red[tid >> 5] = s2;
    __syncthreads();
    float var = 0.f;
    #pragma unroll
    for (int i = 0; i < 8; i++) var += red[i];
    var *= (1.f / 256.f);

    float r = rsqrtf(var + 1e-5f);
    out[(long long)row * HID + tid] = dv * r * g[tid] + bb[tid];
}

// -------------------- per-segment mean combine -----------------------------
// m[b] = mean(y[b,0:512]) - mean(y[b,512:768]) + mean(y[b,768:1024])
__global__ void __launch_bounds__(256) mean_combine_kernel(
    const float* __restrict__ y, float* __restrict__ m)
{
    const int b = blockIdx.x, tid = threadIdx.x;
    const float* base = y + (long long)b * SEQ * HID + tid;
    float a = 0.f, r = 0.f, f = 0.f;
    for (int n = 0;   n < 512;  n++) a += base[(long long)n * HID];
    for (int n = 512; n < 768;  n++) r += base[(long long)n * HID];
    for (int n = 768; n < 1024; n++) f += base[(long long)n * HID];
    m[b * HID + tid] = a * (1.f / 512.f) - r * (1.f / 256.f) + f * (1.f / 256.f);
}

// -------------------- final: out = relu(m @ fc1_W + fc1_b) -----------------
__global__ void __launch_bounds__(256) final_kernel(
    const float* __restrict__ m, const float* __restrict__ W,
    const float* __restrict__ bias, float* __restrict__ out)
{
    const int b = blockIdx.x, j = threadIdx.x;
    __shared__ float sm[HID];
    sm[j] = m[b * HID + j];
    __syncthreads();
    float acc = bias[j];
    #pragma unroll 8
    for (int h = 0; h < HID; h++) acc += sm[h] * W[h * HID + j];
    out[b * HID + j] = fmaxf(acc, 0.f);
}

// ---------------------------------------------------------------------------
static void launch_gemm(const float* A, const float* B, const float* bias,
                        float* C, int M, int N, int K,
                        int lda, int ldb, int ldc,
                        long long sA, long long sB, long long sC,
                        int batch, int relu)
{
    dim3 grid((N + GBN - 1) / GBN, M / GBM, batch);
    gemm_nn<<<grid, 256>>>(A, B, bias, C, M, N, K, lda, ldb, ldc,
                           sA, sB, sC, relu);
}

extern "C" void kernel_launch(void* const* d_in, const int* in_sizes, int n_in,
                              void* d_out, int out_size)
{
    const int*   hyperneigh = (const int*)  d_in[0];
    const float* HT         = (const float*)d_in[1];
    const float* emb        = (const float*)d_in[2];
    const float* Wg1  = (const float*)d_in[3];
    const float* bg1  = (const float*)d_in[4];
    const float* Wg2  = (const float*)d_in[5];
    const float* bg2  = (const float*)d_in[6];
    const float* Wqkv = (const float*)d_in[7];
    const float* bqkv = (const float*)d_in[8];
    const float* Wo   = (const float*)d_in[9];
    const float* bo   = (const float*)d_in[10];
    const float* ln1g = (const float*)d_in[11];
    const float* ln1b = (const float*)d_in[12];
    const float* Wff1 = (const float*)d_in[13];
    const float* bff1 = (const float*)d_in[14];
    const float* Wff2 = (const float*)d_in[15];
    const float* bff2 = (const float*)d_in[16];
    const float* ln2g = (const float*)d_in[17];
    const float* ln2b = (const float*)d_in[18];
    const float* fc1W = (const float*)d_in[19];
    const float* fc1b = (const float*)d_in[20];
    float* out = (float*)d_out;

    float *bufA, *bufB, *bufC, *qkv, *ff, *mbuf;
    cudaGetSymbolAddress((void**)&bufA, g_bufA);
    cudaGetSymbolAddress((void**)&bufB, g_bufB);
    cudaGetSymbolAddress((void**)&bufC, g_bufC);
    cudaGetSymbolAddress((void**)&qkv,  g_qkv);
    cudaGetSymbolAddress((void**)&ff,   g_ff);
    cudaGetSymbolAddress((void**)&mbuf, g_m);

    // 1. gather: bufA = emb[hyperneigh]
    gather_kernel<<<ROWS, 256>>>(hyperneigh, emb, bufA);

    // 2. bufB = bufA @ Wg1
    launch_gemm(bufA, Wg1, nullptr, bufB, ROWS, HID, HID, HID, HID, HID,
                0, 0, 0, 1, 0);
    // 3. bufC = HT @ bufB + bg1   (batched over 16)
    launch_gemm(HT, bufB, bg1, bufC, SEQ, HID, SEQ, SEQ, HID, HID,
                (long long)SEQ * SEQ, (long long)SEQ * HID,
                (long long)SEQ * HID, BATCH, 0);
    // 4. bufB = bufC @ Wg2
    launch_gemm(bufC, Wg2, nullptr, bufB, ROWS, HID, HID, HID, HID, HID,
                0, 0, 0, 1, 0);
    // 5. bufA = HT @ bufB + bg2   -> h2 (encoder input)
    launch_gemm(HT, bufB, bg2, bufA, SEQ, HID, SEQ, SEQ, HID, HID,
                (long long)SEQ * SEQ, (long long)SEQ * HID,
                (long long)SEQ * HID, BATCH, 0);

    // 6. qkv = bufA @ Wqkv + bqkv
    launch_gemm(bufA, Wqkv, bqkv, qkv, ROWS, QKVW, HID, HID, QKVW, QKVW,
                0, 0, 0, 1, 0);

    // 7. attention -> bufB (ctx)
    {
        const int smem_bytes = (64 * 33 + 32 * 68 + 32 * 512) * (int)sizeof(float);
        cudaFuncSetAttribute(attn_kernel,
                             cudaFuncAttributeMaxDynamicSharedMemorySize,
                             smem_bytes);
        attn_kernel<<<dim3(32, 4, BATCH), 256, smem_bytes>>>(qkv, bufB);
    }

    // 8. bufC = bufB @ Wo + bo
    launch_gemm(bufB, Wo, bo, bufC, ROWS, HID, HID, HID, HID, HID,
                0, 0, 0, 1, 0);
    // 9. bufB = LN(bufA + bufC)   -> x
    add_ln_kernel<<<ROWS, 256>>>(bufA, bufC, ln1g, ln1b, bufB);

    // 10. ff = relu(bufB @ Wff1 + bff1)
    launch_gemm(bufB, Wff1, bff1, ff, ROWS, FF, HID, HID, FF, FF,
                0, 0, 0, 1, 1);
    // 11. bufC = ff @ Wff2 + bff2
    launch_gemm(ff, Wff2, bff2, bufC, ROWS, HID, FF, FF, HID, HID,
                0, 0, 0, 1, 0);
    // 12. bufA = LN(bufB + bufC)  -> y
    add_ln_kernel<<<ROWS, 256>>>(bufB, bufC, ln2g, ln2b, bufA);

    // 13. segment means combined, then final fc + relu
    mean_combine_kernel<<<BATCH, 256>>>(bufA, mbuf);
    final_kernel<<<BATCH, 256>>>(mbuf, fc1W, fc1b, out);
}

// round 3
// speedup vs baseline: 1.5449x; 1.5449x over previous
#include <cuda_runtime.h>
#include <cuda_bf16.h>
#include <math.h>
#include <cstdint>

// ---------------------------------------------------------------------------
// GraphEncoder pipeline. GEMMs via legacy tensor-core mma.sync (tf32, f32 acc)
// since the harness targets sm_100 (no -a suffix => no tcgen05).
// B=16, N=1024, H=256, F=400, heads=4, Dh=64.
// ---------------------------------------------------------------------------

#define BATCH 16
#define SEQ   1024
#define HID   256
#define FF    400
#define QKVW  768
#define ROWS  (BATCH * SEQ)          // 16384

// -------------------- scratch (static device memory; no allocs) ------------
__device__ __align__(1024) float g_bufA[ROWS * HID];
__device__ __align__(1024) float g_bufB[ROWS * HID];
__device__ __align__(1024) float g_bufC[ROWS * HID];
__device__ __align__(1024) float g_qkv [ROWS * QKVW];
__device__ __align__(1024) float g_ff  [ROWS * FF];
__device__ float g_m[BATCH * HID];

// -------------------- helpers ----------------------------------------------
__device__ __forceinline__ float tf32r(float x) {
    uint32_t u;
    asm("cvt.rna.tf32.f32 %0, %1;" : "=r"(u) : "f"(x));
    return __uint_as_float(u);
}

__device__ __forceinline__ void mma1688(float* d, const uint32_t* a,
                                        uint32_t b0, uint32_t b1) {
    asm volatile(
        "mma.sync.aligned.m16n8k8.row.col.f32.tf32.tf32.f32 "
        "{%0,%1,%2,%3}, {%4,%5,%6,%7}, {%8,%9}, {%0,%1,%2,%3};\n"
        : "+f"(d[0]), "+f"(d[1]), "+f"(d[2]), "+f"(d[3])
        : "r"(a[0]), "r"(a[1]), "r"(a[2]), "r"(a[3]), "r"(b0), "r"(b1));
}

// -------------------- gather: h0[row] = emb[idx[row]] ----------------------
__global__ void __launch_bounds__(256) gather_kernel(
    const int* __restrict__ idx, const float* __restrict__ emb,
    float* __restrict__ h0)
{
    int row = blockIdx.x, tid = threadIdx.x;
    int e = __ldg(&idx[row]);
    h0[(long long)row * HID + tid] = __ldg(&emb[(long long)e * HID + tid]);
}

// -------------------- tf32 mma.sync GEMM -----------------------------------
// C[M,N] = A[M,K] @ B[K,N] (+bias)(+relu). A,B row-major fp32 (rounded to
// tf32 at smem-store). CTA tile 128x128, BK=16, 8 warps, warp tile 32x64.
#define LDP 132   // padded row length (floats) for both smem tiles

__global__ void __launch_bounds__(256) gemm_mma(
    const float* __restrict__ A, const float* __restrict__ B,
    const float* __restrict__ bias, float* __restrict__ C,
    int M, int N, int K, int lda, int ldb, int ldc,
    long long sA, long long sB, long long sC, int relu)
{
    __shared__ float As[16 * LDP];   // [k][m]  (A transposed into smem)
    __shared__ float Bs[16 * LDP];   // [k][n]

    const long long bz = blockIdx.z;
    A += bz * sA;  B += bz * sB;  C += bz * sC;
    const int m0 = blockIdx.x * 128;
    const int n0 = blockIdx.y * 128;

    const int tid  = threadIdx.x;
    const int wid  = tid >> 5, lane = tid & 31;
    const int g    = lane >> 2, tg = lane & 3;
    const int warpM = wid & 3;          // 4 warps along M (32 rows each)
    const int warpN = wid >> 2;         // 2 warps along N (64 cols each)

    // global-load assignments (2 float4 each for A and B per thread)
    const int arow = tid >> 2;          // 0..63 (+64 second pass)
    const int akq  = tid & 3;           // k-quad within 16
    const int bkr  = tid >> 5;          // 0..7 (+8 second pass)
    const int bnq  = tid & 31;          // n-quad within 128

    float acc[2][8][4];
    #pragma unroll
    for (int mt = 0; mt < 2; mt++)
        #pragma unroll
        for (int nt = 0; nt < 8; nt++)
            #pragma unroll
            for (int i = 0; i < 4; i++) acc[mt][nt][i] = 0.f;

    const int nk = K >> 4;
    float4 aR[2], bR[2];

    // ---- prefetch chunk 0 ----
    {
        #pragma unroll
        for (int i = 0; i < 2; i++)
            aR[i] = *reinterpret_cast<const float4*>(
                &A[(long long)(m0 + arow + i * 64) * lda + akq * 4]);
        #pragma unroll
        for (int i = 0; i < 2; i++) {
            int gn = n0 + bnq * 4;
            bR[i] = (gn < N)
                ? *reinterpret_cast<const float4*>(
                      &B[(long long)(bkr + i * 8) * ldb + gn])
                : make_float4(0.f, 0.f, 0.f, 0.f);
        }
    }

    for (int c = 0; c < nk; c++) {
        if (c) __syncthreads();
        // ---- store chunk c to smem (tf32-rounded) ----
        #pragma unroll
        for (int i = 0; i < 2; i++) {
            int r = arow + i * 64;
            As[(akq * 4 + 0) * LDP + r] = tf32r(aR[i].x);
            As[(akq * 4 + 1) * LDP + r] = tf32r(aR[i].y);
            As[(akq * 4 + 2) * LDP + r] = tf32r(aR[i].z);
            As[(akq * 4 + 3) * LDP + r] = tf32r(aR[i].w);
        }
        #pragma unroll
        for (int i = 0; i < 2; i++) {
            float4 v = bR[i];
            v.x = tf32r(v.x); v.y = tf32r(v.y);
            v.z = tf32r(v.z); v.w = tf32r(v.w);
            *reinterpret_cast<float4*>(&Bs[(bkr + i * 8) * LDP + bnq * 4]) = v;
        }
        // ---- prefetch chunk c+1 ----
        if (c + 1 < nk) {
            const int k0 = (c + 1) * 16;
            #pragma unroll
            for (int i = 0; i < 2; i++)
                aR[i] = *reinterpret_cast<const float4*>(
                    &A[(long long)(m0 + arow + i * 64) * lda + k0 + akq * 4]);
            #pragma unroll
            for (int i = 0; i < 2; i++) {
                int gn = n0 + bnq * 4;
                bR[i] = (gn < N)
                    ? *reinterpret_cast<const float4*>(
                          &B[(long long)(k0 + bkr + i * 8) * ldb + gn])
                    : make_float4(0.f, 0.f, 0.f, 0.f);
            }
        }
        __syncthreads();
        // ---- compute: 2 k-steps of 8 ----
        #pragma unroll
        for (int ks = 0; ks < 2; ks++) {
            const int kb = ks * 8;
            uint32_t a[2][4];
            #pragma unroll
            for (int mt = 0; mt < 2; mt++) {
                const int mr = warpM * 32 + mt * 16;
                a[mt][0] = __float_as_uint(As[(kb + tg)     * LDP + mr + g]);
                a[mt][1] = __float_as_uint(As[(kb + tg)     * LDP + mr + g + 8]);
                a[mt][2] = __float_as_uint(As[(kb + tg + 4) * LDP + mr + g]);
                a[mt][3] = __float_as_uint(As[(kb + tg + 4) * LDP + mr + g + 8]);
            }
            #pragma unroll
            for (int nt = 0; nt < 8; nt++) {
                const int nc = warpN * 64 + nt * 8 + g;
                uint32_t b0 = __float_as_uint(Bs[(kb + tg)     * LDP + nc]);
                uint32_t b1 = __float_as_uint(Bs[(kb + tg + 4) * LDP + nc]);
                mma1688(acc[0][nt], a[0], b0, b1);
                mma1688(acc[1][nt], a[1], b0, b1);
            }
        }
    }

    // ---- epilogue: bias + relu + store (float2 per fragment row) ----
    #pragma unroll
    for (int mt = 0; mt < 2; mt++) {
        #pragma unroll
        for (int nt = 0; nt < 8; nt++) {
            const int row = m0 + warpM * 32 + mt * 16 + g;
            const int col = n0 + warpN * 64 + nt * 8 + 2 * tg;
            if (col >= N) continue;
            float bv0 = bias ? bias[col]     : 0.f;
            float bv1 = bias ? bias[col + 1] : 0.f;
            float v0 = acc[mt][nt][0] + bv0;
            float v1 = acc[mt][nt][1] + bv1;
            float v2 = acc[mt][nt][2] + bv0;
            float v3 = acc[mt][nt][3] + bv1;
            if (relu) {
                v0 = fmaxf(v0, 0.f); v1 = fmaxf(v1, 0.f);
                v2 = fmaxf(v2, 0.f); v3 = fmaxf(v3, 0.f);
            }
            *reinterpret_cast<float2*>(&C[(long long)row * ldc + col]) =
                make_float2(v0, v1);
            *reinterpret_cast<float2*>(&C[(long long)(row + 8) * ldc + col]) =
                make_float2(v2, v3);
        }
    }
}

// -------------------- block-diagonal attention (fp32 SIMT) -----------------
__global__ void __launch_bounds__(256) attn_kernel(
    const float* __restrict__ qkv, float* __restrict__ ctx)
{
    extern __shared__ float smf[];
    const int qt = blockIdx.x, h = blockIdx.y, b = blockIdx.z;
    const int qstart = qt * 32;
    int kstart, S;
    if      (qstart < 512) { kstart = 0;   S = 512; }
    else if (qstart < 768) { kstart = 512; S = 256; }
    else                   { kstart = 768; S = 256; }

    float* sQT = smf;                 // [64][33]
    float* sKV = sQT + 64 * 33;       // [32][68]
    float* sS  = sKV + 32 * 68;       // [32][S]

    const int tid = threadIdx.x;
    const long long rowbase = (long long)(b * SEQ) * QKVW;

    #pragma unroll
    for (int i = 0; i < 8; i++) {
        int flat = tid + i * 256;
        int qi = flat >> 6, d = flat & 63;
        sQT[d * 33 + qi] =
            qkv[rowbase + (long long)(qstart + qi) * QKVW + h * 64 + d];
    }
    __syncthreads();

    const int sqi  = tid & 31;
    const int skj0 = (tid >> 5) * 4;
    for (int kc = 0; kc < S; kc += 32) {
        #pragma unroll
        for (int i = 0; i < 8; i++) {
            int flat = tid + i * 256;
            int ki = flat >> 6, d = flat & 63;
            sKV[ki * 68 + d] =
                qkv[rowbase + (long long)(kstart + kc + ki) * QKVW + 256 + h * 64 + d];
        }
        __syncthreads();
        float a0 = 0.f, a1 = 0.f, a2 = 0.f, a3 = 0.f;
        #pragma unroll 16
        for (int d = 0; d < 64; d++) {
            float qv = sQT[d * 33 + sqi];
            a0 += qv * sKV[(skj0 + 0) * 68 + d];
            a1 += qv * sKV[(skj0 + 1) * 68 + d];
            a2 += qv * sKV[(skj0 + 2) * 68 + d];
            a3 += qv * sKV[(skj0 + 3) * 68 + d];
        }
        sS[sqi * S + kc + skj0 + 0] = a0 * 0.125f;
        sS[sqi * S + kc + skj0 + 1] = a1 * 0.125f;
        sS[sqi * S + kc + skj0 + 2] = a2 * 0.125f;
        sS[sqi * S + kc + skj0 + 3] = a3 * 0.125f;
        __syncthreads();
    }

    {
        const int warp = tid >> 5, ln = tid & 31;
        for (int qi = warp; qi < 32; qi += 8) {
            float* row = sS + qi * S;
            float mx = -1e30f;
            for (int j = ln; j < S; j += 32) mx = fmaxf(mx, row[j]);
            #pragma unroll
            for (int o = 16; o; o >>= 1) mx = fmaxf(mx, __shfl_xor_sync(~0u, mx, o));
            float sum = 0.f;
            for (int j = ln; j < S; j += 32) {
                float e = __expf(row[j] - mx);
                row[j] = e; sum += e;
            }
            #pragma unroll
            for (int o = 16; o; o >>= 1) sum += __shfl_xor_sync(~0u, sum, o);
            float inv = 1.f / sum;
            for (int j = ln; j < S; j += 32) row[j] *= inv;
        }
    }
    __syncthreads();

    const int cqi = tid >> 3;
    const int cd0 = (tid & 7) * 8;
    float acc[8];
    #pragma unroll
    for (int u = 0; u < 8; u++) acc[u] = 0.f;

    for (int kc = 0; kc < S; kc += 32) {
        #pragma unroll
        for (int i = 0; i < 8; i++) {
            int flat = tid + i * 256;
            int ki = flat >> 6, d = flat & 63;
            sKV[ki * 68 + d] =
                qkv[rowbase + (long long)(kstart + kc + ki) * QKVW + 512 + h * 64 + d];
        }
        __syncthreads();
        #pragma unroll 8
        for (int ki = 0; ki < 32; ki++) {
            float p = sS[cqi * S + kc + ki];
            #pragma unroll
            for (int u = 0; u < 8; u++)
                acc[u] += p * sKV[ki * 68 + cd0 + u];
        }
        __syncthreads();
    }

    #pragma unroll
    for (int u = 0; u < 8; u++)
        ctx[(long long)(b * SEQ + qstart + cqi) * HID + h * 64 + cd0 + u] = acc[u];
}

// -------------------- residual add + layernorm -----------------------------
__global__ void __launch_bounds__(256) add_ln_kernel(
    const float* __restrict__ X, const float* __restrict__ Yd,
    const float* __restrict__ g, const float* __restrict__ bb,
    float* __restrict__ out)
{
    const int row = blockIdx.x, tid = threadIdx.x;
    __shared__ float red[8];

    float v = X[(long long)row * HID + tid] + Yd[(long long)row * HID + tid];

    float s = v;
    #pragma unroll
    for (int o = 16; o; o >>= 1) s += __shfl_xor_sync(~0u, s, o);
    if ((tid & 31) == 0) red[tid >> 5] = s;
    __syncthreads();
    float mu = 0.f;
    #pragma unroll
    for (int i = 0; i < 8; i++) mu += red[i];
    mu *= (1.f / 256.f);
    __syncthreads();

    float dv = v - mu;
    float s2 = dv * dv;
    #pragma unroll
    for (int o = 16; o; o >>= 1) s2 += __shfl_xor_sync(~0u, s2, o);
    if ((tid & 31) == 0) red[tid >> 5] = s2;
    __syncthreads();
    float var = 0.f;
    #pragma unroll
    for (int i = 0; i < 8; i++) var += red[i];
    var *= (1.f / 256.f);

    float r = rsqrtf(var + 1e-5f);
    out[(long long)row * HID + tid] = dv * r * g[tid] + bb[tid];
}

// -------------------- per-segment mean combine (parallelized) --------------
__global__ void __launch_bounds__(1024) mean_combine_kernel(
    const float* __restrict__ y, float* __restrict__ m)
{
    const int b = blockIdx.x, tid = threadIdx.x;
    const int c = tid & 255, rg = tid >> 8;       // 4 row-groups of 256 rows
    const float* base = y + (long long)b * SEQ * HID + c;
    float acc = 0.f;
    const int r0 = rg * 256;
    #pragma unroll 4
    for (int n = r0; n < r0 + 256; n++) {
        float w = (n < 512) ? (1.f / 512.f)
                : ((n < 768) ? (-1.f / 256.f) : (1.f / 256.f));
        acc += w * base[(long long)n * HID];
    }
    __shared__ float red[4][256];
    red[rg][c] = acc;
    __syncthreads();
    if (rg == 0)
        m[b * HID + c] = red[0][c] + red[1][c] + red[2][c] + red[3][c];
}

// -------------------- final: out = relu(m @ fc1_W + fc1_b) -----------------
__global__ void __launch_bounds__(256) final_kernel(
    const float* __restrict__ m, const float* __restrict__ W,
    const float* __restrict__ bias, float* __restrict__ out)
{
    const int b = blockIdx.x, j = threadIdx.x;
    __shared__ float sm[HID];
    sm[j] = m[b * HID + j];
    __syncthreads();
    float acc = bias[j];
    #pragma unroll 8
    for (int h = 0; h < HID; h++) acc += sm[h] * W[h * HID + j];
    out[b * HID + j] = fmaxf(acc, 0.f);
}

// ---------------------------------------------------------------------------
static void launch_gemm(const float* A, const float* B, const float* bias,
                        float* C, int M, int N, int K,
                        int lda, int ldb, int ldc,
                        long long sA, long long sB, long long sC,
                        int batch, int relu)
{
    dim3 grid(M / 128, (N + 127) / 128, batch);
    gemm_mma<<<grid, 256>>>(A, B, bias, C, M, N, K, lda, ldb, ldc,
                            sA, sB, sC, relu);
}

extern "C" void kernel_launch(void* const* d_in, const int* in_sizes, int n_in,
                              void* d_out, int out_size)
{
    const int*   hyperneigh = (const int*)  d_in[0];
    const float* HT         = (const float*)d_in[1];
    const float* emb        = (const float*)d_in[2];
    const float* Wg1  = (const float*)d_in[3];
    const float* bg1  = (const float*)d_in[4];
    const float* Wg2  = (const float*)d_in[5];
    const float* bg2  = (const float*)d_in[6];
    const float* Wqkv = (const float*)d_in[7];
    const float* bqkv = (const float*)d_in[8];
    const float* Wo   = (const float*)d_in[9];
    const float* bo   = (const float*)d_in[10];
    const float* ln1g = (const float*)d_in[11];
    const float* ln1b = (const float*)d_in[12];
    const float* Wff1 = (const float*)d_in[13];
    const float* bff1 = (const float*)d_in[14];
    const float* Wff2 = (const float*)d_in[15];
    const float* bff2 = (const float*)d_in[16];
    const float* ln2g = (const float*)d_in[17];
    const float* ln2b = (const float*)d_in[18];
    const float* fc1W = (const float*)d_in[19];
    const float* fc1b = (const float*)d_in[20];
    float* out = (float*)d_out;

    float *bufA, *bufB, *bufC, *qkv, *ff, *mbuf;
    cudaGetSymbolAddress((void**)&bufA, g_bufA);
    cudaGetSymbolAddress((void**)&bufB, g_bufB);
    cudaGetSymbolAddress((void**)&bufC, g_bufC);
    cudaGetSymbolAddress((void**)&qkv,  g_qkv);
    cudaGetSymbolAddress((void**)&ff,   g_ff);
    cudaGetSymbolAddress((void**)&mbuf, g_m);

    // 1. gather
    gather_kernel<<<ROWS, 256>>>(hyperneigh, emb, bufA);

    // 2. bufB = bufA @ Wg1
    launch_gemm(bufA, Wg1, nullptr, bufB, ROWS, HID, HID, HID, HID, HID,
                0, 0, 0, 1, 0);
    // 3. bufC = HT @ bufB + bg1   (batched over 16)
    launch_gemm(HT, bufB, bg1, bufC, SEQ, HID, SEQ, SEQ, HID, HID,
                (long long)SEQ * SEQ, (long long)SEQ * HID,
                (long long)SEQ * HID, BATCH, 0);
    // 4. bufB = bufC @ Wg2
    launch_gemm(bufC, Wg2, nullptr, bufB, ROWS, HID, HID, HID, HID, HID,
                0, 0, 0, 1, 0);
    // 5. bufA = HT @ bufB + bg2
    launch_gemm(HT, bufB, bg2, bufA, SEQ, HID, SEQ, SEQ, HID, HID,
                (long long)SEQ * SEQ, (long long)SEQ * HID,
                (long long)SEQ * HID, BATCH, 0);

    // 6. qkv = bufA @ Wqkv + bqkv
    launch_gemm(bufA, Wqkv, bqkv, qkv, ROWS, QKVW, HID, HID, QKVW, QKVW,
                0, 0, 0, 1, 0);

    // 7. attention -> bufB (ctx)
    {
        const int smem_bytes = (64 * 33 + 32 * 68 + 32 * 512) * (int)sizeof(float);
        cudaFuncSetAttribute(attn_kernel,
                             cudaFuncAttributeMaxDynamicSharedMemorySize, smem_bytes);
        attn_kernel<<<dim3(32, 4, BATCH), 256, smem_bytes>>>(qkv, bufB);
    }

    // 8. bufC = bufB @ Wo + bo
    launch_gemm(bufB, Wo, bo, bufC, ROWS, HID, HID, HID, HID, HID,
                0, 0, 0, 1, 0);
    // 9. bufB = LN(bufA + bufC)
    add_ln_kernel<<<ROWS, 256>>>(bufA, bufC, ln1g, ln1b, bufB);

    // 10. ff = relu(bufB @ Wff1 + bff1)
    launch_gemm(bufB, Wff1, bff1, ff, ROWS, FF, HID, HID, FF, FF,
                0, 0, 0, 1, 1);
    // 11. bufC = ff @ Wff2 + bff2
    launch_gemm(ff, Wff2, bff2, bufC, ROWS, HID, FF, FF, HID, HID,
                0, 0, 0, 1, 0);
    // 12. bufA = LN(bufB + bufC)
    add_ln_kernel<<<ROWS, 256>>>(bufB, bufC, ln2g, ln2b, bufA);

    // 13. segment means combined, then final fc + relu
    mean_combine_kernel<<<BATCH, 1024>>>(bufA, mbuf);
    final_kernel<<<BATCH, 256>>>(mbuf, fc1W, fc1b, out);
}

// round 7
// speedup vs baseline: 2.4993x; 1.6178x over previous
#include <cuda_runtime.h>
#include <cuda_bf16.h>
#include <math.h>
#include <cstdint>

// ---------------------------------------------------------------------------
// GraphEncoder pipeline. GEMMs + attention via mma.sync (tf32, f32 accum).
// B=16, N=1024, H=256, F=400, heads=4, Dh=64.
// ---------------------------------------------------------------------------

#define BATCH 16
#define SEQ   1024
#define HID   256
#define FF    400
#define QKVW  768
#define ROWS  (BATCH * SEQ)          // 16384

// -------------------- scratch (static device memory; no allocs) ------------
__device__ __align__(1024) float g_bufA[ROWS * HID];
__device__ __align__(1024) float g_bufB[ROWS * HID];
__device__ __align__(1024) float g_bufC[ROWS * HID];
__device__ __align__(1024) float g_qkv [ROWS * QKVW];
__device__ __align__(1024) float g_ff  [ROWS * FF];
__device__ float g_m[BATCH * HID];

// -------------------- helpers ----------------------------------------------
__device__ __forceinline__ float tf32r(float x) {
    uint32_t u;
    asm("cvt.rna.tf32.f32 %0, %1;" : "=r"(u) : "f"(x));
    return __uint_as_float(u);
}

__device__ __forceinline__ void mma1688(float* d, const uint32_t* a,
                                        uint32_t b0, uint32_t b1) {
    asm volatile(
        "mma.sync.aligned.m16n8k8.row.col.f32.tf32.tf32.f32 "
        "{%0,%1,%2,%3}, {%4,%5,%6,%7}, {%8,%9}, {%0,%1,%2,%3};\n"
        : "+f"(d[0]), "+f"(d[1]), "+f"(d[2]), "+f"(d[3])
        : "r"(a[0]), "r"(a[1]), "r"(a[2]), "r"(a[3]), "r"(b0), "r"(b1));
}

// -------------------- gather: h0[row] = emb[idx[row]] ----------------------
__global__ void __launch_bounds__(256) gather_kernel(
    const int* __restrict__ idx, const float* __restrict__ emb,
    float* __restrict__ h0)
{
    int row = blockIdx.x, tid = threadIdx.x;
    int e = __ldg(&idx[row]);
    h0[(long long)row * HID + tid] = __ldg(&emb[(long long)e * HID + tid]);
}

// -------------------- tf32 mma.sync GEMM (passing in R3) -------------------
#define LDP 132

__global__ void __launch_bounds__(256) gemm_mma(
    const float* __restrict__ A, const float* __restrict__ B,
    const float* __restrict__ bias, float* __restrict__ C,
    int M, int N, int K, int lda, int ldb, int ldc,
    long long sA, long long sB, long long sC, int relu)
{
    __shared__ float As[16 * LDP];
    __shared__ float Bs[16 * LDP];

    const long long bz = blockIdx.z;
    A += bz * sA;  B += bz * sB;  C += bz * sC;
    const int m0 = blockIdx.x * 128;
    const int n0 = blockIdx.y * 128;

    const int tid  = threadIdx.x;
    const int wid  = tid >> 5, lane = tid & 31;
    const int g    = lane >> 2, tg = lane & 3;
    const int warpM = wid & 3;
    const int warpN = wid >> 2;

    const int arow = tid >> 2;
    const int akq  = tid & 3;
    const int bkr  = tid >> 5;
    const int bnq  = tid & 31;

    float acc[2][8][4];
    #pragma unroll
    for (int mt = 0; mt < 2; mt++)
        #pragma unroll
        for (int nt = 0; nt < 8; nt++)
            #pragma unroll
            for (int i = 0; i < 4; i++) acc[mt][nt][i] = 0.f;

    const int nk = K >> 4;
    float4 aR[2], bR[2];

    {
        #pragma unroll
        for (int i = 0; i < 2; i++)
            aR[i] = *reinterpret_cast<const float4*>(
                &A[(long long)(m0 + arow + i * 64) * lda + akq * 4]);
        #pragma unroll
        for (int i = 0; i < 2; i++) {
            int gn = n0 + bnq * 4;
            bR[i] = (gn < N)
                ? *reinterpret_cast<const float4*>(
                      &B[(long long)(bkr + i * 8) * ldb + gn])
                : make_float4(0.f, 0.f, 0.f, 0.f);
        }
    }

    for (int c = 0; c < nk; c++) {
        if (c) __syncthreads();
        #pragma unroll
        for (int i = 0; i < 2; i++) {
            int r = arow + i * 64;
            As[(akq * 4 + 0) * LDP + r] = tf32r(aR[i].x);
            As[(akq * 4 + 1) * LDP + r] = tf32r(aR[i].y);
            As[(akq * 4 + 2) * LDP + r] = tf32r(aR[i].z);
            As[(akq * 4 + 3) * LDP + r] = tf32r(aR[i].w);
        }
        #pragma unroll
        for (int i = 0; i < 2; i++) {
            float4 v = bR[i];
            v.x = tf32r(v.x); v.y = tf32r(v.y);
            v.z = tf32r(v.z); v.w = tf32r(v.w);
            *reinterpret_cast<float4*>(&Bs[(bkr + i * 8) * LDP + bnq * 4]) = v;
        }
        if (c + 1 < nk) {
            const int k0 = (c + 1) * 16;
            #pragma unroll
            for (int i = 0; i < 2; i++)
                aR[i] = *reinterpret_cast<const float4*>(
                    &A[(long long)(m0 + arow + i * 64) * lda + k0 + akq * 4]);
            #pragma unroll
            for (int i = 0; i < 2; i++) {
                int gn = n0 + bnq * 4;
                bR[i] = (gn < N)
                    ? *reinterpret_cast<const float4*>(
                          &B[(long long)(k0 + bkr + i * 8) * ldb + gn])
                    : make_float4(0.f, 0.f, 0.f, 0.f);
            }
        }
        __syncthreads();
        #pragma unroll
        for (int ks = 0; ks < 2; ks++) {
            const int kb = ks * 8;
            uint32_t a[2][4];
            #pragma unroll
            for (int mt = 0; mt < 2; mt++) {
                const int mr = warpM * 32 + mt * 16;
                a[mt][0] = __float_as_uint(As[(kb + tg)     * LDP + mr + g]);
                a[mt][1] = __float_as_uint(As[(kb + tg)     * LDP + mr + g + 8]);
                a[mt][2] = __float_as_uint(As[(kb + tg + 4) * LDP + mr + g]);
                a[mt][3] = __float_as_uint(As[(kb + tg + 4) * LDP + mr + g + 8]);
            }
            #pragma unroll
            for (int nt = 0; nt < 8; nt++) {
                const int nc = warpN * 64 + nt * 8 + g;
                uint32_t b0 = __float_as_uint(Bs[(kb + tg)     * LDP + nc]);
                uint32_t b1 = __float_as_uint(Bs[(kb + tg + 4) * LDP + nc]);
                mma1688(acc[0][nt], a[0], b0, b1);
                mma1688(acc[1][nt], a[1], b0, b1);
            }
        }
    }

    #pragma unroll
    for (int mt = 0; mt < 2; mt++) {
        #pragma unroll
        for (int nt = 0; nt < 8; nt++) {
            const int row = m0 + warpM * 32 + mt * 16 + g;
            const int col = n0 + warpN * 64 + nt * 8 + 2 * tg;
            if (col >= N) continue;
            float bv0 = bias ? bias[col]     : 0.f;
            float bv1 = bias ? bias[col + 1] : 0.f;
            float v0 = acc[mt][nt][0] + bv0;
            float v1 = acc[mt][nt][1] + bv1;
            float v2 = acc[mt][nt][2] + bv0;
            float v3 = acc[mt][nt][3] + bv1;
            if (relu) {
                v0 = fmaxf(v0, 0.f); v1 = fmaxf(v1, 0.f);
                v2 = fmaxf(v2, 0.f); v3 = fmaxf(v3, 0.f);
            }
            *reinterpret_cast<float2*>(&C[(long long)row * ldc + col]) =
                make_float2(v0, v1);
            *reinterpret_cast<float2*>(&C[(long long)(row + 8) * ldc + col]) =
                make_float2(v2, v3);
        }
    }
}

// -------------------- block-diagonal attention via mma.sync ----------------
// Block: 32 queries x one (b,h). 256 threads / 8 warps.
// Warp w: m-tile = (w&1)*16, n-tiles = (w>>1)*16 + {0,8}.
// smem: sQ[32][68] | sKV[64][68] (K chunk, then Vt) | sS[32][516]
#define SSTR 516
#define ATTN_SMEM ((32 * 68 + 64 * 68 + 32 * SSTR) * 4)

__global__ void __launch_bounds__(256) attn_kernel(
    const float* __restrict__ qkv, float* __restrict__ ctx)
{
    extern __shared__ float sm[];
    float* sQ  = sm;
    float* sKV = sm + 32 * 68;
    float* sS  = sKV + 64 * 68;

    const int qt = blockIdx.x, h = blockIdx.y, b = blockIdx.z;
    const int qstart = qt * 32;
    int kstart, S;
    if      (qstart < 512) { kstart = 0;   S = 512; }
    else if (qstart < 768) { kstart = 512; S = 256; }
    else                   { kstart = 768; S = 256; }
    const int nch = S >> 6;

    const int tid = threadIdx.x, wid = tid >> 5, lane = tid & 31;
    const int g = lane >> 2, tg = lane & 3;
    const int mw  = (wid & 1) * 16;
    const int nb0 = (wid >> 1) * 16;
    const long long rowbase = (long long)(b * SEQ) * QKVW;

    // ---- load Q tile [32][64], tf32-rounded ----
    {
        int qi = tid >> 3, d0 = (tid & 7) * 8;
        const float* src = &qkv[rowbase + (long long)(qstart + qi) * QKVW + h * 64 + d0];
        float4 v0 = *reinterpret_cast<const float4*>(src);
        float4 v1 = *reinterpret_cast<const float4*>(src + 4);
        float* dst = &sQ[qi * 68 + d0];
        dst[0] = tf32r(v0.x); dst[1] = tf32r(v0.y);
        dst[2] = tf32r(v0.z); dst[3] = tf32r(v0.w);
        dst[4] = tf32r(v1.x); dst[5] = tf32r(v1.y);
        dst[6] = tf32r(v1.z); dst[7] = tf32r(v1.w);
    }

    // ---- QK^T: chunks of 64 keys ----
    for (int c = 0; c < nch; c++) {
        __syncthreads();
        {
            int kl = tid >> 2, d0 = (tid & 3) * 16;
            const float* src = &qkv[rowbase +
                (long long)(kstart + c * 64 + kl) * QKVW + 256 + h * 64 + d0];
            float* dst = &sKV[kl * 68 + d0];
            #pragma unroll
            for (int i = 0; i < 4; i++) {
                float4 v = *reinterpret_cast<const float4*>(src + i * 4);
                dst[i * 4 + 0] = tf32r(v.x); dst[i * 4 + 1] = tf32r(v.y);
                dst[i * 4 + 2] = tf32r(v.z); dst[i * 4 + 3] = tf32r(v.w);
            }
        }
        __syncthreads();

        float s0[4] = {0.f, 0.f, 0.f, 0.f};
        float s1[4] = {0.f, 0.f, 0.f, 0.f};
        #pragma unroll
        for (int ks = 0; ks < 8; ks++) {
            const int kb = ks * 8;
            uint32_t a[4];
            a[0] = __float_as_uint(sQ[(mw + g)     * 68 + kb + tg]);
            a[1] = __float_as_uint(sQ[(mw + g + 8) * 68 + kb + tg]);
            a[2] = __float_as_uint(sQ[(mw + g)     * 68 + kb + tg + 4]);
            a[3] = __float_as_uint(sQ[(mw + g + 8) * 68 + kb + tg + 4]);
            uint32_t b0 = __float_as_uint(sKV[(nb0 + g) * 68 + kb + tg]);
            uint32_t b1 = __float_as_uint(sKV[(nb0 + g) * 68 + kb + tg + 4]);
            mma1688(s0, a, b0, b1);
            b0 = __float_as_uint(sKV[(nb0 + 8 + g) * 68 + kb + tg]);
            b1 = __float_as_uint(sKV[(nb0 + 8 + g) * 68 + kb + tg + 4]);
            mma1688(s1, a, b0, b1);
        }
        const int col0 = c * 64 + nb0 + 2 * tg;
        const int r0 = mw + g, r1 = mw + g + 8;
        sS[r0 * SSTR + col0]     = s0[0] * 0.125f;
        sS[r0 * SSTR + col0 + 1] = s0[1] * 0.125f;
        sS[r1 * SSTR + col0]     = s0[2] * 0.125f;
        sS[r1 * SSTR + col0 + 1] = s0[3] * 0.125f;
        sS[r0 * SSTR + col0 + 8] = s1[0] * 0.125f;
        sS[r0 * SSTR + col0 + 9] = s1[1] * 0.125f;
        sS[r1 * SSTR + col0 + 8] = s1[2] * 0.125f;
        sS[r1 * SSTR + col0 + 9] = s1[3] * 0.125f;
    }
    __syncthreads();

    // ---- softmax per row; normalized probs rounded to tf32 ----
    for (int qi = wid; qi < 32; qi += 8) {
        float* row = sS + qi * SSTR;
        float mx = -1e30f;
        for (int j = lane; j < S; j += 32) mx = fmaxf(mx, row[j]);
        #pragma unroll
        for (int o = 16; o; o >>= 1) mx = fmaxf(mx, __shfl_xor_sync(~0u, mx, o));
        float sum = 0.f;
        for (int j = lane; j < S; j += 32) {
            float e = __expf(row[j] - mx);
            row[j] = e; sum += e;
        }
        #pragma unroll
        for (int o = 16; o; o >>= 1) sum += __shfl_xor_sync(~0u, sum, o);
        float inv = 1.f / sum;
        for (int j = lane; j < S; j += 32) row[j] = tf32r(row[j] * inv);
    }

    // ---- P @ V: chunks of 64 keys, accumulators persist ----
    float p0[4] = {0.f, 0.f, 0.f, 0.f};
    float p1[4] = {0.f, 0.f, 0.f, 0.f};
    for (int c = 0; c < nch; c++) {
        __syncthreads();
        #pragma unroll
        for (int i = 0; i < 8; i++) {
            int s = wid * 8 + i;
            const float* src = &qkv[rowbase +
                (long long)(kstart + c * 64 + s) * QKVW + 512 + h * 64];
            float v0 = src[lane];
            float v1 = src[lane + 32];
            sKV[lane * 68 + s]        = tf32r(v0);
            sKV[(lane + 32) * 68 + s] = tf32r(v1);
        }
        __syncthreads();
        #pragma unroll
        for (int ks = 0; ks < 8; ks++) {
            const int kb = ks * 8;
            const int kc = c * 64 + kb;
            uint32_t a[4];
            a[0] = __float_as_uint(sS[(mw + g)     * SSTR + kc + tg]);
            a[1] = __float_as_uint(sS[(mw + g + 8) * SSTR + kc + tg]);
            a[2] = __float_as_uint(sS[(mw + g)     * SSTR + kc + tg + 4]);
            a[3] = __float_as_uint(sS[(mw + g + 8) * SSTR + kc + tg + 4]);
            uint32_t b0 = __float_as_uint(sKV[(nb0 + g) * 68 + kb + tg]);
            uint32_t b1 = __float_as_uint(sKV[(nb0 + g) * 68 + kb + tg + 4]);
            mma1688(p0, a, b0, b1);
            b0 = __float_as_uint(sKV[(nb0 + 8 + g) * 68 + kb + tg]);
            b1 = __float_as_uint(sKV[(nb0 + 8 + g) * 68 + kb + tg + 4]);
            mma1688(p1, a, b0, b1);
        }
    }

    // ---- write ctx ----
    {
        const long long r0 = (long long)(b * SEQ + qstart + mw + g);
        const int cc = h * 64 + nb0 + 2 * tg;
        *reinterpret_cast<float2*>(&ctx[r0 * HID + cc]) =
            make_float2(p0[0], p0[1]);
        *reinterpret_cast<float2*>(&ctx[(r0 + 8) * HID + cc]) =
            make_float2(p0[2], p0[3]);
        *reinterpret_cast<float2*>(&ctx[r0 * HID + cc + 8]) =
            make_float2(p1[0], p1[1]);
        *reinterpret_cast<float2*>(&ctx[(r0 + 8) * HID + cc + 8]) =
            make_float2(p1[2], p1[3]);
    }
}

// -------------------- residual add + layernorm -----------------------------
__global__ void __launch_bounds__(256) add_ln_kernel(
    const float* __restrict__ X, const float* __restrict__ Yd,
    const float* __restrict__ g, const float* __restrict__ bb,
    float* __restrict__ out)
{
    const int row = blockIdx.x, tid = threadIdx.x;
    __shared__ float red[8];

    float v = X[(long long)row * HID + tid] + Yd[(long long)row * HID + tid];

    float s = v;
    #pragma unroll
    for (int o = 16; o; o >>= 1) s += __shfl_xor_sync(~0u, s, o);
    if ((tid & 31) == 0) red[tid >> 5] = s;
    __syncthreads();
    float mu = 0.f;
    #pragma unroll
    for (int i = 0; i < 8; i++) mu += red[i];
    mu *= (1.f / 256.f);
    __syncthreads();

    float dv = v - mu;
    float s2 = dv * dv;
    #pragma unroll
    for (int o = 16; o; o >>= 1) s2 += __shfl_xor_sync(~0u, s2, o);
    if ((tid & 31) == 0) red[tid >> 5] = s2;
    __syncthreads();
    float var = 0.f;
    #pragma unroll
    for (int i = 0; i < 8; i++) var += red[i];
    var *= (1.f / 256.f);

    float r = rsqrtf(var + 1e-5f);
    out[(long long)row * HID + tid] = dv * r * g[tid] + bb[tid];
}

// -------------------- per-segment mean combine -----------------------------
__global__ void __launch_bounds__(1024) mean_combine_kernel(
    const float* __restrict__ y, float* __restrict__ m)
{
    const int b = blockIdx.x, tid = threadIdx.x;
    const int c = tid & 255, rg = tid >> 8;
    const float* base = y + (long long)b * SEQ * HID + c;
    float acc = 0.f;
    const int r0 = rg * 256;
    #pragma unroll 4
    for (int n = r0; n < r0 + 256; n++) {
        float w = (n < 512) ? (1.f / 512.f)
                : ((n < 768) ? (-1.f / 256.f) : (1.f / 256.f));
        acc += w * base[(long long)n * HID];
    }
    __shared__ float red[4][256];
    red[rg][c] = acc;
    __syncthreads();
    if (rg == 0)
        m[b * HID + c] = red[0][c] + red[1][c] + red[2][c] + red[3][c];
}

// -------------------- final: out = relu(m @ fc1_W + fc1_b) -----------------
__global__ void __launch_bounds__(256) final_kernel(
    const float* __restrict__ m, const float* __restrict__ W,
    const float* __restrict__ bias, float* __restrict__ out)
{
    const int b = blockIdx.x, j = threadIdx.x;
    __shared__ float sm[HID];
    sm[j] = m[b * HID + j];
    __syncthreads();
    float acc = bias[j];
    #pragma unroll 8
    for (int h = 0; h < HID; h++) acc += sm[h] * W[h * HID + j];
    out[b * HID + j] = fmaxf(acc, 0.f);
}

// ---------------------------------------------------------------------------
static void launch_gemm(const float* A, const float* B, const float* bias,
                        float* C, int M, int N, int K,
                        int lda, int ldb, int ldc,
                        long long sA, long long sB, long long sC,
                        int batch, int relu)
{
    dim3 grid(M / 128, (N + 127) / 128, batch);
    gemm_mma<<<grid, 256>>>(A, B, bias, C, M, N, K, lda, ldb, ldc,
                            sA, sB, sC, relu);
}

extern "C" void kernel_launch(void* const* d_in, const int* in_sizes, int n_in,
                              void* d_out, int out_size)
{
    const int*   hyperneigh = (const int*)  d_in[0];
    const float* HT         = (const float*)d_in[1];
    const float* emb        = (const float*)d_in[2];
    const float* Wg1  = (const float*)d_in[3];
    const float* bg1  = (const float*)d_in[4];
    const float* Wg2  = (const float*)d_in[5];
    const float* bg2  = (const float*)d_in[6];
    const float* Wqkv = (const float*)d_in[7];
    const float* bqkv = (const float*)d_in[8];
    const float* Wo   = (const float*)d_in[9];
    const float* bo   = (const float*)d_in[10];
    const float* ln1g = (const float*)d_in[11];
    const float* ln1b = (const float*)d_in[12];
    const float* Wff1 = (const float*)d_in[13];
    const float* bff1 = (const float*)d_in[14];
    const float* Wff2 = (const float*)d_in[15];
    const float* bff2 = (const float*)d_in[16];
    const float* ln2g = (const float*)d_in[17];
    const float* ln2b = (const float*)d_in[18];
    const float* fc1W = (const float*)d_in[19];
    const float* fc1b = (const float*)d_in[20];
    float* out = (float*)d_out;

    float *bufA, *bufB, *bufC, *qkv, *ff, *mbuf;
    cudaGetSymbolAddress((void**)&bufA, g_bufA);
    cudaGetSymbolAddress((void**)&bufB, g_bufB);
    cudaGetSymbolAddress((void**)&bufC, g_bufC);
    cudaGetSymbolAddress((void**)&qkv,  g_qkv);
    cudaGetSymbolAddress((void**)&ff,   g_ff);
    cudaGetSymbolAddress((void**)&mbuf, g_m);

    // 1. gather
    gather_kernel<<<ROWS, 256>>>(hyperneigh, emb, bufA);

    // 2. bufB = bufA @ Wg1
    launch_gemm(bufA, Wg1, nullptr, bufB, ROWS, HID, HID, HID, HID, HID,
                0, 0, 0, 1, 0);
    // 3. bufC = HT @ bufB + bg1
    launch_gemm(HT, bufB, bg1, bufC, SEQ, HID, SEQ, SEQ, HID, HID,
                (long long)SEQ * SEQ, (long long)SEQ * HID,
                (long long)SEQ * HID, BATCH, 0);
    // 4. bufB = bufC @ Wg2
    launch_gemm(bufC, Wg2, nullptr, bufB, ROWS, HID, HID, HID, HID, HID,
                0, 0, 0, 1, 0);
    // 5. bufA = HT @ bufB + bg2
    launch_gemm(HT, bufB, bg2, bufA, SEQ, HID, SEQ, SEQ, HID, HID,
                (long long)SEQ * SEQ, (long long)SEQ * HID,
                (long long)SEQ * HID, BATCH, 0);

    // 6. qkv = bufA @ Wqkv + bqkv
    launch_gemm(bufA, Wqkv, bqkv, qkv, ROWS, QKVW, HID, HID, QKVW, QKVW,
                0, 0, 0, 1, 0);

    // 7. attention -> bufB (ctx)
    {
        cudaFuncSetAttribute(attn_kernel,
                             cudaFuncAttributeMaxDynamicSharedMemorySize,
                             ATTN_SMEM);
        attn_kernel<<<dim3(32, 4, BATCH), 256, ATTN_SMEM>>>(qkv, bufB);
    }

    // 8. bufC = bufB @ Wo + bo
    launch_gemm(bufB, Wo, bo, bufC, ROWS, HID, HID, HID, HID, HID,
                0, 0, 0, 1, 0);
    // 9. bufB = LN(bufA + bufC)
    add_ln_kernel<<<ROWS, 256>>>(bufA, bufC, ln1g, ln1b, bufB);

    // 10. ff = relu(bufB @ Wff1 + bff1)
    launch_gemm(bufB, Wff1, bff1, ff, ROWS, FF, HID, HID, FF, FF,
                0, 0, 0, 1, 1);
    // 11. bufC = ff @ Wff2 + bff2
    launch_gemm(ff, Wff2, bff2, bufC, ROWS, HID, FF, FF, HID, HID,
                0, 0, 0, 1, 0);
    // 12. bufA = LN(bufB + bufC)
    add_ln_kernel<<<ROWS, 256>>>(bufB, bufC, ln2g, ln2b, bufA);

    // 13. segment means combined, then final fc + relu
    mean_combine_kernel<<<BATCH, 1024>>>(bufA, mbuf);
    final_kernel<<<BATCH, 256>>>(mbuf, fc1W, fc1b, out);
}

// round 8
// speedup vs baseline: 2.9524x; 1.1813x over previous
#include <cuda_runtime.h>
#include <cuda_bf16.h>
#include <math.h>
#include <cstdint>

// ---------------------------------------------------------------------------
// GraphEncoder pipeline. GEMMs + attention via mma.sync (tf32, f32 accum).
// GEMM mainloop: 3-stage cp.async pipeline, HW tf32 truncation.
// B=16, N=1024, H=256, F=400, heads=4, Dh=64.
// ---------------------------------------------------------------------------

#define BATCH 16
#define SEQ   1024
#define HID   256
#define FF    400
#define QKVW  768
#define ROWS  (BATCH * SEQ)          // 16384

// -------------------- scratch (static device memory; no allocs) ------------
__device__ __align__(1024) float g_bufA[ROWS * HID];
__device__ __align__(1024) float g_bufB[ROWS * HID];
__device__ __align__(1024) float g_bufC[ROWS * HID];
__device__ __align__(1024) float g_qkv [ROWS * QKVW];
__device__ __align__(1024) float g_ff  [ROWS * FF];
__device__ float g_m[BATCH * HID];

// -------------------- helpers ----------------------------------------------
__device__ __forceinline__ float tf32r(float x) {
    uint32_t u;
    asm("cvt.rna.tf32.f32 %0, %1;" : "=r"(u) : "f"(x));
    return __uint_as_float(u);
}

__device__ __forceinline__ void mma1688(float* d, const uint32_t* a,
                                        uint32_t b0, uint32_t b1) {
    asm volatile(
        "mma.sync.aligned.m16n8k8.row.col.f32.tf32.tf32.f32 "
        "{%0,%1,%2,%3}, {%4,%5,%6,%7}, {%8,%9}, {%0,%1,%2,%3};\n"
        : "+f"(d[0]), "+f"(d[1]), "+f"(d[2]), "+f"(d[3])
        : "r"(a[0]), "r"(a[1]), "r"(a[2]), "r"(a[3]), "r"(b0), "r"(b1));
}

__device__ __forceinline__ uint32_t s2u(const void* p) {
    return (uint32_t)__cvta_generic_to_shared(p);
}
#define CP_ASYNC16(dst, src) \
    asm volatile("cp.async.ca.shared.global [%0], [%1], 16;" :: "r"(dst), "l"(src))
#define CP_COMMIT() asm volatile("cp.async.commit_group;" ::: "memory")
#define CP_WAIT1()  asm volatile("cp.async.wait_group 1;" ::: "memory")

// -------------------- gather: h0[row] = emb[idx[row]] ----------------------
__global__ void __launch_bounds__(256) gather_kernel(
    const int* __restrict__ idx, const float* __restrict__ emb,
    float* __restrict__ h0)
{
    int row = blockIdx.x, tid = threadIdx.x;
    int e = __ldg(&idx[row]);
    h0[(long long)row * HID + tid] = __ldg(&emb[(long long)e * HID + tid]);
}

// -------------------- tf32 mma.sync GEMM, cp.async pipelined ---------------
// C[M,N] = A[M,K] @ B[K,N] (+bias)(+relu). CTA tile 128x128, BK=16,
// 8 warps, warp tile 32x64. 3-stage cp.async double... triple buffering.
// As: [128 rows][20 floats] (16 used, pad 20 -> conflict-free frag LDS)
// Bs: [16 k-rows][132 floats] (128 used)
#define AST 20
#define BST 132
#define A_FLTS (128 * AST)           // 2560
#define B_FLTS (16 * BST)            // 2112
#define STG_FLTS (A_FLTS + B_FLTS)   // 4672
#define GEMM_SMEM (3 * STG_FLTS * 4) // 56064 bytes

__global__ void __launch_bounds__(256) gemm_mma(
    const float* __restrict__ A, const float* __restrict__ B,
    const float* __restrict__ bias, float* __restrict__ C,
    int M, int N, int K, int lda, int ldb, int ldc,
    long long sA, long long sB, long long sC, int relu)
{
    extern __shared__ float smem2[];

    const long long bz = blockIdx.z;
    A += bz * sA;  B += bz * sB;  C += bz * sC;
    const int m0 = blockIdx.x * 128;
    const int n0 = blockIdx.y * 128;

    const int tid  = threadIdx.x;
    const int wid  = tid >> 5, lane = tid & 31;
    const int g    = lane >> 2, tg = lane & 3;
    const int warpM = wid & 3;
    const int warpN = wid >> 2;

    const uint32_t sbase = s2u(smem2);
    const int nk = K >> 4;

    // per-thread cp.async assignments
    const int ar0 = tid >> 2, aq = tid & 3;      // A: row, 16B-quad (2 passes)
    const int br0 = tid >> 5, bq = tid & 31;     // B: k-row, 16B-quad (2 passes)

    // ---- stage issue helper (inlined via lambda-like macro style) ----
    auto issue_stage = [&](int c) {
        const int stg = c % 3;
        const uint32_t abase = sbase + stg * STG_FLTS * 4;
        const uint32_t bbase = abase + A_FLTS * 4;
        const int k0 = c * 16;
        #pragma unroll
        for (int i = 0; i < 2; i++) {
            int r = ar0 + i * 64;
            CP_ASYNC16(abase + (uint32_t)(r * AST + aq * 4) * 4,
                       &A[(long long)(m0 + r) * lda + k0 + aq * 4]);
        }
        #pragma unroll
        for (int i = 0; i < 2; i++) {
            int r = br0 + i * 8;
            int gn = n0 + bq * 4;
            if (gn < N)
                CP_ASYNC16(bbase + (uint32_t)(r * BST + bq * 4) * 4,
                           &B[(long long)(k0 + r) * ldb + gn]);
        }
    };

    float acc[2][8][4];
    #pragma unroll
    for (int mt = 0; mt < 2; mt++)
        #pragma unroll
        for (int nt = 0; nt < 8; nt++)
            #pragma unroll
            for (int i = 0; i < 4; i++) acc[mt][nt][i] = 0.f;

    // ---- prologue: stages 0,1 in flight ----
    issue_stage(0); CP_COMMIT();
    issue_stage(1); CP_COMMIT();

    for (int c = 0; c < nk; c++) {
        CP_WAIT1();                 // stage c landed
        __syncthreads();            // all warps past compute(c-1), see stage c
        if (c + 2 < nk) issue_stage(c + 2);   // into buf (c-1)%3 — safe
        CP_COMMIT();                // empty group ok, keeps counts aligned

        const int stg = c % 3;
        const float* As = smem2 + stg * STG_FLTS;
        const float* Bs = As + A_FLTS;

        #pragma unroll
        for (int ks = 0; ks < 2; ks++) {
            const int kb = ks * 8;
            uint32_t a[2][4];
            #pragma unroll
            for (int mt = 0; mt < 2; mt++) {
                const int mr = warpM * 32 + mt * 16;
                a[mt][0] = __float_as_uint(As[(mr + g)     * AST + kb + tg]);
                a[mt][1] = __float_as_uint(As[(mr + g + 8) * AST + kb + tg]);
                a[mt][2] = __float_as_uint(As[(mr + g)     * AST + kb + tg + 4]);
                a[mt][3] = __float_as_uint(As[(mr + g + 8) * AST + kb + tg + 4]);
            }
            #pragma unroll
            for (int nt = 0; nt < 8; nt++) {
                const int nc = warpN * 64 + nt * 8 + g;
                uint32_t b0 = __float_as_uint(Bs[(kb + tg)     * BST + nc]);
                uint32_t b1 = __float_as_uint(Bs[(kb + tg + 4) * BST + nc]);
                mma1688(acc[0][nt], a[0], b0, b1);
                mma1688(acc[1][nt], a[1], b0, b1);
            }
        }
    }

    // ---- epilogue: bias + relu + float2 stores ----
    #pragma unroll
    for (int mt = 0; mt < 2; mt++) {
        #pragma unroll
        for (int nt = 0; nt < 8; nt++) {
            const int row = m0 + warpM * 32 + mt * 16 + g;
            const int col = n0 + warpN * 64 + nt * 8 + 2 * tg;
            if (col >= N) continue;
            float bv0 = bias ? bias[col]     : 0.f;
            float bv1 = bias ? bias[col + 1] : 0.f;
            float v0 = acc[mt][nt][0] + bv0;
            float v1 = acc[mt][nt][1] + bv1;
            float v2 = acc[mt][nt][2] + bv0;
            float v3 = acc[mt][nt][3] + bv1;
            if (relu) {
                v0 = fmaxf(v0, 0.f); v1 = fmaxf(v1, 0.f);
                v2 = fmaxf(v2, 0.f); v3 = fmaxf(v3, 0.f);
            }
            *reinterpret_cast<float2*>(&C[(long long)row * ldc + col]) =
                make_float2(v0, v1);
            *reinterpret_cast<float2*>(&C[(long long)(row + 8) * ldc + col]) =
                make_float2(v2, v3);
        }
    }
}

// -------------------- block-diagonal attention via mma.sync ----------------
// Block: 32 queries x one (b,h). 256 threads / 8 warps.
// Warp w: m-tile = (w&1)*16, n-tiles = (w>>1)*16 + {0,8}.
// smem: sQ[32][68] | sKV[64][68] (K chunk, then Vt) | sS[32][516]
#define SSTR 516
#define ATTN_SMEM ((32 * 68 + 64 * 68 + 32 * SSTR) * 4)

__global__ void __launch_bounds__(256) attn_kernel(
    const float* __restrict__ qkv, float* __restrict__ ctx)
{
    extern __shared__ float sm[];
    float* sQ  = sm;
    float* sKV = sm + 32 * 68;
    float* sS  = sKV + 64 * 68;

    const int qt = blockIdx.x, h = blockIdx.y, b = blockIdx.z;
    const int qstart = qt * 32;
    int kstart, S;
    if      (qstart < 512) { kstart = 0;   S = 512; }
    else if (qstart < 768) { kstart = 512; S = 256; }
    else                   { kstart = 768; S = 256; }
    const int nch = S >> 6;

    const int tid = threadIdx.x, wid = tid >> 5, lane = tid & 31;
    const int g = lane >> 2, tg = lane & 3;
    const int mw  = (wid & 1) * 16;
    const int nb0 = (wid >> 1) * 16;
    const long long rowbase = (long long)(b * SEQ) * QKVW;

    // ---- load Q tile [32][64], tf32-rounded ----
    {
        int qi = tid >> 3, d0 = (tid & 7) * 8;
        const float* src = &qkv[rowbase + (long long)(qstart + qi) * QKVW + h * 64 + d0];
        float4 v0 = *reinterpret_cast<const float4*>(src);
        float4 v1 = *reinterpret_cast<const float4*>(src + 4);
        float* dst = &sQ[qi * 68 + d0];
        dst[0] = tf32r(v0.x); dst[1] = tf32r(v0.y);
        dst[2] = tf32r(v0.z); dst[3] = tf32r(v0.w);
        dst[4] = tf32r(v1.x); dst[5] = tf32r(v1.y);
        dst[6] = tf32r(v1.z); dst[7] = tf32r(v1.w);
    }

    // ---- QK^T: chunks of 64 keys ----
    for (int c = 0; c < nch; c++) {
        __syncthreads();
        {
            int kl = tid >> 2, d0 = (tid & 3) * 16;
            const float* src = &qkv[rowbase +
                (long long)(kstart + c * 64 + kl) * QKVW + 256 + h * 64 + d0];
            float* dst = &sKV[kl * 68 + d0];
            #pragma unroll
            for (int i = 0; i < 4; i++) {
                float4 v = *reinterpret_cast<const float4*>(src + i * 4);
                dst[i * 4 + 0] = tf32r(v.x); dst[i * 4 + 1] = tf32r(v.y);
                dst[i * 4 + 2] = tf32r(v.z); dst[i * 4 + 3] = tf32r(v.w);
            }
        }
        __syncthreads();

        float s0[4] = {0.f, 0.f, 0.f, 0.f};
        float s1[4] = {0.f, 0.f, 0.f, 0.f};
        #pragma unroll
        for (int ks = 0; ks < 8; ks++) {
            const int kb = ks * 8;
            uint32_t a[4];
            a[0] = __float_as_uint(sQ[(mw + g)     * 68 + kb + tg]);
            a[1] = __float_as_uint(sQ[(mw + g + 8) * 68 + kb + tg]);
            a[2] = __float_as_uint(sQ[(mw + g)     * 68 + kb + tg + 4]);
            a[3] = __float_as_uint(sQ[(mw + g + 8) * 68 + kb + tg + 4]);
            uint32_t b0 = __float_as_uint(sKV[(nb0 + g) * 68 + kb + tg]);
            uint32_t b1 = __float_as_uint(sKV[(nb0 + g) * 68 + kb + tg + 4]);
            mma1688(s0, a, b0, b1);
            b0 = __float_as_uint(sKV[(nb0 + 8 + g) * 68 + kb + tg]);
            b1 = __float_as_uint(sKV[(nb0 + 8 + g) * 68 + kb + tg + 4]);
            mma1688(s1, a, b0, b1);
        }
        const int col0 = c * 64 + nb0 + 2 * tg;
        const int r0 = mw + g, r1 = mw + g + 8;
        sS[r0 * SSTR + col0]     = s0[0] * 0.125f;
        sS[r0 * SSTR + col0 + 1] = s0[1] * 0.125f;
        sS[r1 * SSTR + col0]     = s0[2] * 0.125f;
        sS[r1 * SSTR + col0 + 1] = s0[3] * 0.125f;
        sS[r0 * SSTR + col0 + 8] = s1[0] * 0.125f;
        sS[r0 * SSTR + col0 + 9] = s1[1] * 0.125f;
        sS[r1 * SSTR + col0 + 8] = s1[2] * 0.125f;
        sS[r1 * SSTR + col0 + 9] = s1[3] * 0.125f;
    }
    __syncthreads();

    // ---- softmax per row; normalized probs rounded to tf32 ----
    for (int qi = wid; qi < 32; qi += 8) {
        float* row = sS + qi * SSTR;
        float mx = -1e30f;
        for (int j = lane; j < S; j += 32) mx = fmaxf(mx, row[j]);
        #pragma unroll
        for (int o = 16; o; o >>= 1) mx = fmaxf(mx, __shfl_xor_sync(~0u, mx, o));
        float sum = 0.f;
        for (int j = lane; j < S; j += 32) {
            float e = __expf(row[j] - mx);
            row[j] = e; sum += e;
        }
        #pragma unroll
        for (int o = 16; o; o >>= 1) sum += __shfl_xor_sync(~0u, sum, o);
        float inv = 1.f / sum;
        for (int j = lane; j < S; j += 32) row[j] = tf32r(row[j] * inv);
    }

    // ---- P @ V: chunks of 64 keys, accumulators persist ----
    float p0[4] = {0.f, 0.f, 0.f, 0.f};
    float p1[4] = {0.f, 0.f, 0.f, 0.f};
    for (int c = 0; c < nch; c++) {
        __syncthreads();
        #pragma unroll
        for (int i = 0; i < 8; i++) {
            int s = wid * 8 + i;
            const float* src = &qkv[rowbase +
                (long long)(kstart + c * 64 + s) * QKVW + 512 + h * 64];
            float v0 = src[lane];
            float v1 = src[lane + 32];
            sKV[lane * 68 + s]        = tf32r(v0);
            sKV[(lane + 32) * 68 + s] = tf32r(v1);
        }
        __syncthreads();
        #pragma unroll
        for (int ks = 0; ks < 8; ks++) {
            const int kb = ks * 8;
            const int kc = c * 64 + kb;
            uint32_t a[4];
            a[0] = __float_as_uint(sS[(mw + g)     * SSTR + kc + tg]);
            a[1] = __float_as_uint(sS[(mw + g + 8) * SSTR + kc + tg]);
            a[2] = __float_as_uint(sS[(mw + g)     * SSTR + kc + tg + 4]);
            a[3] = __float_as_uint(sS[(mw + g + 8) * SSTR + kc + tg + 4]);
            uint32_t b0 = __float_as_uint(sKV[(nb0 + g) * 68 + kb + tg]);
            uint32_t b1 = __float_as_uint(sKV[(nb0 + g) * 68 + kb + tg + 4]);
            mma1688(p0, a, b0, b1);
            b0 = __float_as_uint(sKV[(nb0 + 8 + g) * 68 + kb + tg]);
            b1 = __float_as_uint(sKV[(nb0 + 8 + g) * 68 + kb + tg + 4]);
            mma1688(p1, a, b0, b1);
        }
    }

    // ---- write ctx ----
    {
        const long long r0 = (long long)(b * SEQ + qstart + mw + g);
        const int cc = h * 64 + nb0 + 2 * tg;
        *reinterpret_cast<float2*>(&ctx[r0 * HID + cc]) =
            make_float2(p0[0], p0[1]);
        *reinterpret_cast<float2*>(&ctx[(r0 + 8) * HID + cc]) =
            make_float2(p0[2], p0[3]);
        *reinterpret_cast<float2*>(&ctx[r0 * HID + cc + 8]) =
            make_float2(p1[0], p1[1]);
        *reinterpret_cast<float2*>(&ctx[(r0 + 8) * HID + cc + 8]) =
            make_float2(p1[2], p1[3]);
    }
}

// -------------------- residual add + layernorm -----------------------------
__global__ void __launch_bounds__(256) add_ln_kernel(
    const float* __restrict__ X, const float* __restrict__ Yd,
    const float* __restrict__ g, const float* __restrict__ bb,
    float* __restrict__ out)
{
    const int row = blockIdx.x, tid = threadIdx.x;
    __shared__ float red[8];

    float v = X[(long long)row * HID + tid] + Yd[(long long)row * HID + tid];

    float s = v;
    #pragma unroll
    for (int o = 16; o; o >>= 1) s += __shfl_xor_sync(~0u, s, o);
    if ((tid & 31) == 0) red[tid >> 5] = s;
    __syncthreads();
    float mu = 0.f;
    #pragma unroll
    for (int i = 0; i < 8; i++) mu += red[i];
    mu *= (1.f / 256.f);
    __syncthreads();

    float dv = v - mu;
    float s2 = dv * dv;
    #pragma unroll
    for (int o = 16; o; o >>= 1) s2 += __shfl_xor_sync(~0u, s2, o);
    if ((tid & 31) == 0) red[tid >> 5] = s2;
    __syncthreads();
    float var = 0.f;
    #pragma unroll
    for (int i = 0; i < 8; i++) var += red[i];
    var *= (1.f / 256.f);

    float r = rsqrtf(var + 1e-5f);
    out[(long long)row * HID + tid] = dv * r * g[tid] + bb[tid];
}

// -------------------- per-segment mean combine -----------------------------
__global__ void __launch_bounds__(1024) mean_combine_kernel(
    const float* __restrict__ y, float* __restrict__ m)
{
    const int b = blockIdx.x, tid = threadIdx.x;
    const int c = tid & 255, rg = tid >> 8;
    const float* base = y + (long long)b * SEQ * HID + c;
    float acc = 0.f;
    const int r0 = rg * 256;
    #pragma unroll 4
    for (int n = r0; n < r0 + 256; n++) {
        float w = (n < 512) ? (1.f / 512.f)
                : ((n < 768) ? (-1.f / 256.f) : (1.f / 256.f));
        acc += w * base[(long long)n * HID];
    }
    __shared__ float red[4][256];
    red[rg][c] = acc;
    __syncthreads();
    if (rg == 0)
        m[b * HID + c] = red[0][c] + red[1][c] + red[2][c] + red[3][c];
}

// -------------------- final: out = relu(m @ fc1_W + fc1_b) -----------------
__global__ void __launch_bounds__(256) final_kernel(
    const float* __restrict__ m, const float* __restrict__ W,
    const float* __restrict__ bias, float* __restrict__ out)
{
    const int b = blockIdx.x, j = threadIdx.x;
    __shared__ float sm[HID];
    sm[j] = m[b * HID + j];
    __syncthreads();
    float acc = bias[j];
    #pragma unroll 8
    for (int h = 0; h < HID; h++) acc += sm[h] * W[h * HID + j];
    out[b * HID + j] = fmaxf(acc, 0.f);
}

// ---------------------------------------------------------------------------
static void launch_gemm(const float* A, const float* B, const float* bias,
                        float* C, int M, int N, int K,
                        int lda, int ldb, int ldc,
                        long long sA, long long sB, long long sC,
                        int batch, int relu)
{
    static bool attr_set = false;
    if (!attr_set) {
        cudaFuncSetAttribute(gemm_mma,
                             cudaFuncAttributeMaxDynamicSharedMemorySize,
                             GEMM_SMEM);
        attr_set = true;
    }
    dim3 grid(M / 128, (N + 127) / 128, batch);
    gemm_mma<<<grid, 256, GEMM_SMEM>>>(A, B, bias, C, M, N, K, lda, ldb, ldc,
                                       sA, sB, sC, relu);
}

extern "C" void kernel_launch(void* const* d_in, const int* in_sizes, int n_in,
                              void* d_out, int out_size)
{
    const int*   hyperneigh = (const int*)  d_in[0];
    const float* HT         = (const float*)d_in[1];
    const float* emb        = (const float*)d_in[2];
    const float* Wg1  = (const float*)d_in[3];
    const float* bg1  = (const float*)d_in[4];
    const float* Wg2  = (const float*)d_in[5];
    const float* bg2  = (const float*)d_in[6];
    const float* Wqkv = (const float*)d_in[7];
    const float* bqkv = (const float*)d_in[8];
    const float* Wo   = (const float*)d_in[9];
    const float* bo   = (const float*)d_in[10];
    const float* ln1g = (const float*)d_in[11];
    const float* ln1b = (const float*)d_in[12];
    const float* Wff1 = (const float*)d_in[13];
    const float* bff1 = (const float*)d_in[14];
    const float* Wff2 = (const float*)d_in[15];
    const float* bff2 = (const float*)d_in[16];
    const float* ln2g = (const float*)d_in[17];
    const float* ln2b = (const float*)d_in[18];
    const float* fc1W = (const float*)d_in[19];
    const float* fc1b = (const float*)d_in[20];
    float* out = (float*)d_out;

    float *bufA, *bufB, *bufC, *qkv, *ff, *mbuf;
    cudaGetSymbolAddress((void**)&bufA, g_bufA);
    cudaGetSymbolAddress((void**)&bufB, g_bufB);
    cudaGetSymbolAddress((void**)&bufC, g_bufC);
    cudaGetSymbolAddress((void**)&qkv,  g_qkv);
    cudaGetSymbolAddress((void**)&ff,   g_ff);
    cudaGetSymbolAddress((void**)&mbuf, g_m);

    // 1. gather
    gather_kernel<<<ROWS, 256>>>(hyperneigh, emb, bufA);

    // 2. bufB = bufA @ Wg1
    launch_gemm(bufA, Wg1, nullptr, bufB, ROWS, HID, HID, HID, HID, HID,
                0, 0, 0, 1, 0);
    // 3. bufC = HT @ bufB + bg1
    launch_gemm(HT, bufB, bg1, bufC, SEQ, HID, SEQ, SEQ, HID, HID,
                (long long)SEQ * SEQ, (long long)SEQ * HID,
                (long long)SEQ * HID, BATCH, 0);
    // 4. bufB = bufC @ Wg2
    launch_gemm(bufC, Wg2, nullptr, bufB, ROWS, HID, HID, HID, HID, HID,
                0, 0, 0, 1, 0);
    // 5. bufA = HT @ bufB + bg2
    launch_gemm(HT, bufB, bg2, bufA, SEQ, HID, SEQ, SEQ, HID, HID,
                (long long)SEQ * SEQ, (long long)SEQ * HID,
                (long long)SEQ * HID, BATCH, 0);

    // 6. qkv = bufA @ Wqkv + bqkv
    launch_gemm(bufA, Wqkv, bqkv, qkv, ROWS, QKVW, HID, HID, QKVW, QKVW,
                0, 0, 0, 1, 0);

    // 7. attention -> bufB (ctx)
    {
        cudaFuncSetAttribute(attn_kernel,
                             cudaFuncAttributeMaxDynamicSharedMemorySize,
                             ATTN_SMEM);
        attn_kernel<<<dim3(32, 4, BATCH), 256, ATTN_SMEM>>>(qkv, bufB);
    }

    // 8. bufC = bufB @ Wo + bo
    launch_gemm(bufB, Wo, bo, bufC, ROWS, HID, HID, HID, HID, HID,
                0, 0, 0, 1, 0);
    // 9. bufB = LN(bufA + bufC)
    add_ln_kernel<<<ROWS, 256>>>(bufA, bufC, ln1g, ln1b, bufB);

    // 10. ff = relu(bufB @ Wff1 + bff1)
    launch_gemm(bufB, Wff1, bff1, ff, ROWS, FF, HID, HID, FF, FF,
                0, 0, 0, 1, 1);
    // 11. bufC = ff @ Wff2 + bff2
    launch_gemm(ff, Wff2, bff2, bufC, ROWS, HID, FF, FF, HID, HID,
                0, 0, 0, 1, 0);
    // 12. bufA = LN(bufB + bufC)
    add_ln_kernel<<<ROWS, 256>>>(bufB, bufC, ln2g, ln2b, bufA);

    // 13. segment means combined, then final fc + relu
    mean_combine_kernel<<<BATCH, 1024>>>(bufA, mbuf);
    final_kernel<<<BATCH, 256>>>(mbuf, fc1W, fc1b, out);
}